// round 1
// baseline (speedup 1.0000x reference)
#include <cuda_runtime.h>
#include <cuda_bf16.h>
#include <math.h>

// ---------------- problem constants ----------------
#define D_MODEL 192
#define D_STATE 16
#define D_CONV  4
#define D_INNER 384
#define DT_RANK 12
#define BB      4
#define HH      32
#define WW      32
#define NN      1024          // H*W
#define NPAIR   16            // 4 dirs * 4 batches
#define ROWS    (BB*NN)       // 4096
#define DBL_W   (DT_RANK + 2*D_STATE)  // 44

// ---------------- scratch (device globals; no allocs allowed) ----------------
__device__ float g_XS  [ROWS * D_MODEL];            // post-LN input (also residual)
__device__ float g_XP  [ROWS * D_MODEL];            // after in_w proj
__device__ float g_U   [NPAIR * NN * D_MODEL];      // 4-direction sequences
__device__ float g_XZ  [NPAIR * NN * 2 * D_INNER];  // in-proj (xh | z)
__device__ float g_XSM [NPAIR * NN * D_INNER];      // silu(conv(xh))
__device__ float g_DBL [NPAIR * NN * DBL_W];        // (dt_low | B | C)
__device__ float g_DT  [NPAIR * NN * D_INNER];      // softplus(dt)
__device__ float g_Y   [NPAIR * NN * D_INNER];      // scan output
__device__ float g_YG  [NPAIR * NN * D_INNER];      // gated
__device__ float g_OUTD[NPAIR * NN * D_MODEL];      // per-direction out proj
__device__ float g_FUS [ROWS * 4 * D_MODEL];        // fused 768
__device__ float g_H1  [ROWS * 2 * D_MODEL];        // 384
__device__ float g_H2  [ROWS * D_MODEL];
__device__ float g_H3  [ROWS * D_MODEL];

// ---------------- helpers ----------------
__device__ __forceinline__ float siluf(float x) { return x / (1.0f + expf(-x)); }

// block reduce for 192 threads (6 warps): sum of (a,b)
__device__ __forceinline__ void block_reduce2_192(float& a, float& b) {
    #pragma unroll
    for (int o = 16; o > 0; o >>= 1) {
        a += __shfl_xor_sync(0xffffffffu, a, o);
        b += __shfl_xor_sync(0xffffffffu, b, o);
    }
    __shared__ float sa[6], sb[6];
    int w = threadIdx.x >> 5, l = threadIdx.x & 31;
    if (l == 0) { sa[w] = a; sb[w] = b; }
    __syncthreads();
    if (threadIdx.x == 0) {
        float ta = 0.f, tb = 0.f;
        #pragma unroll
        for (int i = 0; i < 6; i++) { ta += sa[i]; tb += sb[i]; }
        sa[0] = ta; sb[0] = tb;
    }
    __syncthreads();
    a = sa[0]; b = sb[0];
}

// ---------------- LN over input x (B,192,N) -> XS (B*N,192) ----------------
__global__ void ln_in_kernel(const float* __restrict__ x,
                             const float* __restrict__ g,
                             const float* __restrict__ b,
                             float* __restrict__ XS) {
    int row = blockIdx.x;               // b*N + n
    int bb = row >> 10, n = row & 1023;
    int c = threadIdx.x;                // 0..191
    float v = x[((long)bb * D_MODEL + c) * NN + n];
    float s = v, s2 = v * v;
    block_reduce2_192(s, s2);
    float mean = s * (1.0f / D_MODEL);
    float var = s2 * (1.0f / D_MODEL) - mean * mean;
    float rstd = rsqrtf(var + 1e-5f);
    XS[(long)row * D_MODEL + c] = (v - mean) * rstd * g[c] + b[c];
}

// ---------------- generic batched GEMM: C = A(MxK) * Bw(NxK)^T (+bias)(+act) ----
// act: 0 none, 2 gelu-exact
__global__ __launch_bounds__(256) void gemm_abt(
    const float* __restrict__ A, const float* __restrict__ Bw,
    const float* __restrict__ bias, float* __restrict__ C,
    int M, int N, int K, long sA, long sB, long sC, int bdiv, int act)
{
    int bz = blockIdx.z;
    const float* Ab = A + (long)bz * sA;
    const float* Bb = Bw + (long)(bz / bdiv) * sB;
    float* Cb = C + (long)bz * sC;

    __shared__ float As[16][64];
    __shared__ float Bs[16][64];

    int t = threadIdx.x;
    int tr = t >> 4, tc = t & 15;
    int m0 = blockIdx.y << 6, n0 = blockIdx.x << 6;

    int lm = t >> 2;           // 0..63
    int lk = (t & 3) << 2;     // 0,4,8,12

    float acc[4][4] = {};
    int nK = K >> 4;           // K is always a multiple of 16 here
    for (int kb = 0; kb < nK; kb++) {
        int k0 = kb << 4;
        float4 av = make_float4(0.f, 0.f, 0.f, 0.f);
        float4 bv = make_float4(0.f, 0.f, 0.f, 0.f);
        if (m0 + lm < M) av = *(const float4*)(Ab + (long)(m0 + lm) * K + k0 + lk);
        if (n0 + lm < N) bv = *(const float4*)(Bb + (long)(n0 + lm) * K + k0 + lk);
        __syncthreads();
        As[lk + 0][lm] = av.x; As[lk + 1][lm] = av.y; As[lk + 2][lm] = av.z; As[lk + 3][lm] = av.w;
        Bs[lk + 0][lm] = bv.x; Bs[lk + 1][lm] = bv.y; Bs[lk + 2][lm] = bv.z; Bs[lk + 3][lm] = bv.w;
        __syncthreads();
        #pragma unroll
        for (int kk = 0; kk < 16; kk++) {
            float4 a4 = *(const float4*)&As[kk][tr << 2];
            float4 b4 = *(const float4*)&Bs[kk][tc << 2];
            float ar[4] = {a4.x, a4.y, a4.z, a4.w};
            float br[4] = {b4.x, b4.y, b4.z, b4.w};
            #pragma unroll
            for (int i = 0; i < 4; i++)
                #pragma unroll
                for (int j = 0; j < 4; j++)
                    acc[i][j] += ar[i] * br[j];
        }
    }
    #pragma unroll
    for (int i = 0; i < 4; i++) {
        int m = m0 + (tr << 2) + i;
        if (m >= M) continue;
        #pragma unroll
        for (int j = 0; j < 4; j++) {
            int n = n0 + (tc << 2) + j;
            if (n >= N) continue;
            float v = acc[i][j];
            if (bias) v += bias[n];
            if (act == 2) v = 0.5f * v * (1.0f + erff(v * 0.70710678118654752f));
            Cb[(long)m * N + n] = v;
        }
    }
}

// ---------------- build 4-direction sequences U from XP ----------------
__global__ void build_u_kernel(const float* __restrict__ XP, float* __restrict__ U) {
    long idx = (long)blockIdx.x * blockDim.x + threadIdx.x; // up to 16*1024*192
    int c = (int)(idx % D_MODEL);
    int t = (int)((idx / D_MODEL) & 1023);
    int gp = (int)(idx / ((long)D_MODEL * NN));
    int k = gp >> 2, bb = gp & 3;
    int src;
    if (k == 0)      src = t;
    else if (k == 1) src = 1023 - t;
    else if (k == 2) src = ((t & 31) << 5) | (t >> 5);
    else { int tt = 1023 - t; src = ((tt & 31) << 5) | (tt >> 5); }
    U[idx] = XP[((long)bb * NN + src) * D_MODEL + c];
}

// ---------------- depthwise causal conv(4) + bias + silu ----------------
__global__ void conv_silu_kernel(const float* __restrict__ XZ,
                                 const float* __restrict__ cw,
                                 const float* __restrict__ cb,
                                 float* __restrict__ XSM) {
    long idx = (long)blockIdx.x * blockDim.x + threadIdx.x; // 16*1024*384
    int d = (int)(idx % D_INNER);
    int t = (int)((idx / D_INNER) & 1023);
    int gp = (int)(idx / ((long)D_INNER * NN));
    int k = gp >> 2;
    const float* base = XZ + ((long)gp * NN) * (2 * D_INNER) + d;
    const float* w = cw + ((long)k * D_INNER + d) * D_CONV;
    float acc = cb[k * D_INNER + d];
    #pragma unroll
    for (int j = 0; j < 4; j++) {
        int tau = t - 3 + j;
        if (tau >= 0) acc += w[j] * base[(long)tau * (2 * D_INNER)];
    }
    XSM[idx] = siluf(acc);
}

// ---------------- dt = softplus(dt_low @ Wdt^T + bdt) ----------------
__global__ void dt_kernel(const float* __restrict__ DBL,
                          const float* __restrict__ wdt,
                          const float* __restrict__ bdt,
                          float* __restrict__ DT) {
    long idx = (long)blockIdx.x * blockDim.x + threadIdx.x; // 16*1024*384
    int d = (int)(idx % D_INNER);
    long rt = idx / D_INNER;              // gp*1024 + t
    int gp = (int)(rt >> 10);
    int k = gp >> 2;
    const float* row = DBL + rt * DBL_W;
    const float* w = wdt + ((long)k * D_INNER + d) * DT_RANK;
    float s = bdt[k * D_INNER + d];
    #pragma unroll
    for (int r = 0; r < DT_RANK; r++) s += row[r] * w[r];
    DT[idx] = (s > 20.0f) ? s : log1pf(expf(s));
}

// ---------------- sequential selective scan ----------------
// 16 lanes per channel (lane = state), 128 threads = 8 channels/block
__global__ void scan_kernel(const float* __restrict__ DT,
                            const float* __restrict__ XSM,
                            const float* __restrict__ DBL,
                            const float* __restrict__ Alog,
                            float* __restrict__ Y) {
    int gp = blockIdx.z;                 // 0..15
    int k = gp >> 2;
    int lane = threadIdx.x & 15;         // state
    int d = (blockIdx.x << 3) + (threadIdx.x >> 4);
    float A = -expf(Alog[((long)k * D_INNER + d) * D_STATE + lane]);
    const float* dtp = DT  + ((long)gp * NN) * D_INNER + d;
    const float* xp_ = XSM + ((long)gp * NN) * D_INNER + d;
    const float* bp  = DBL + ((long)gp * NN) * DBL_W + DT_RANK + lane;
    const float* cp  = bp + D_STATE;
    float* yp = Y + ((long)gp * NN) * D_INNER + d;
    float h = 0.f;
    for (int t = 0; t < NN; t++) {
        float dt = dtp[(long)t * D_INNER];
        float xv = xp_[(long)t * D_INNER];
        float Bv = bp[(long)t * DBL_W];
        float Cv = cp[(long)t * DBL_W];
        float dA = __expf(dt * A);
        h = dA * h + (dt * xv) * Bv;
        float p = h * Cv;
        p += __shfl_xor_sync(0xffffffffu, p, 1);
        p += __shfl_xor_sync(0xffffffffu, p, 2);
        p += __shfl_xor_sync(0xffffffffu, p, 4);
        p += __shfl_xor_sync(0xffffffffu, p, 8);
        if (lane == 0) yp[(long)t * D_INNER] = p;
    }
}

// ---------------- y = (y + xsm*D) * silu(z) ----------------
__global__ void combine_kernel(const float* __restrict__ Y,
                               const float* __restrict__ XSM,
                               const float* __restrict__ XZ,
                               const float* __restrict__ Dp,
                               float* __restrict__ YG) {
    long idx = (long)blockIdx.x * blockDim.x + threadIdx.x; // 16*1024*384
    int d = (int)(idx % D_INNER);
    long rt = idx / D_INNER;
    int gp = (int)(rt >> 10);
    int k = gp >> 2;
    float z = XZ[rt * (2 * D_INNER) + D_INNER + d];
    YG[idx] = (Y[idx] + XSM[idx] * Dp[k * D_INNER + d]) * siluf(z);
}

// ---------------- gather 4 directions into fused (B*N, 768) ----------------
__global__ void gather_kernel(const float* __restrict__ OUTD, float* __restrict__ FUS) {
    long idx = (long)blockIdx.x * blockDim.x + threadIdx.x; // 4096*768
    int col = (int)(idx % (4 * D_MODEL));
    long r = idx / (4 * D_MODEL);        // b*1024 + n
    int k = col / D_MODEL, c = col % D_MODEL;
    int bb = (int)(r >> 10), n = (int)(r & 1023);
    int t;
    if (k == 0)      t = n;
    else if (k == 1) t = 1023 - n;
    else if (k == 2) t = ((n & 31) << 5) | (n >> 5);
    else             t = 1023 - (((n & 31) << 5) | (n >> 5));
    FUS[idx] = OUTD[(((long)(k * 4 + bb) * NN) + t) * D_MODEL + c];
}

// ---------------- final LN + residual + transpose to (B,192,H,W) -----------
__global__ void ln_out_kernel(const float* __restrict__ H3,
                              const float* __restrict__ g,
                              const float* __restrict__ b,
                              const float* __restrict__ XS,
                              float* __restrict__ out) {
    int row = blockIdx.x;                // b*N + n
    int bb = row >> 10, n = row & 1023;
    int c = threadIdx.x;
    float v = H3[(long)row * D_MODEL + c];
    float s = v, s2 = v * v;
    block_reduce2_192(s, s2);
    float mean = s * (1.0f / D_MODEL);
    float var = s2 * (1.0f / D_MODEL) - mean * mean;
    float rstd = rsqrtf(var + 1e-5f);
    float r = (v - mean) * rstd * g[c] + b[c] + XS[(long)row * D_MODEL + c];
    out[((long)bb * D_MODEL + c) * NN + n] = r;
}

// ---------------- host launch ----------------
extern "C" void kernel_launch(void* const* d_in, const int* in_sizes, int n_in,
                              void* d_out, int out_size) {
    const float* x      = (const float*)d_in[0];
    const float* norm_g = (const float*)d_in[1];
    const float* norm_b = (const float*)d_in[2];
    const float* in_w   = (const float*)d_in[3];
    const float* in_b   = (const float*)d_in[4];
    const float* m_in_w = (const float*)d_in[5];
    const float* m_cw   = (const float*)d_in[6];
    const float* m_cb   = (const float*)d_in[7];
    const float* m_xp_w = (const float*)d_in[8];
    const float* m_dt_w = (const float*)d_in[9];
    const float* m_dt_b = (const float*)d_in[10];
    const float* m_Alog = (const float*)d_in[11];
    const float* m_D    = (const float*)d_in[12];
    const float* m_out_w= (const float*)d_in[13];
    const float* f_w1   = (const float*)d_in[14];
    const float* f_b1   = (const float*)d_in[15];
    const float* f_w2   = (const float*)d_in[16];
    const float* f_b2   = (const float*)d_in[17];
    const float* o_w    = (const float*)d_in[18];
    const float* o_b    = (const float*)d_in[19];
    const float* on_g   = (const float*)d_in[20];
    const float* on_b   = (const float*)d_in[21];
    float* out = (float*)d_out;

    float *XS, *XP, *U, *XZ, *XSM, *DBL, *DT, *Y, *YG, *OUTD, *FUS, *H1, *H2, *H3;
    cudaGetSymbolAddress((void**)&XS,   g_XS);
    cudaGetSymbolAddress((void**)&XP,   g_XP);
    cudaGetSymbolAddress((void**)&U,    g_U);
    cudaGetSymbolAddress((void**)&XZ,   g_XZ);
    cudaGetSymbolAddress((void**)&XSM,  g_XSM);
    cudaGetSymbolAddress((void**)&DBL,  g_DBL);
    cudaGetSymbolAddress((void**)&DT,   g_DT);
    cudaGetSymbolAddress((void**)&Y,    g_Y);
    cudaGetSymbolAddress((void**)&YG,   g_YG);
    cudaGetSymbolAddress((void**)&OUTD, g_OUTD);
    cudaGetSymbolAddress((void**)&FUS,  g_FUS);
    cudaGetSymbolAddress((void**)&H1,   g_H1);
    cudaGetSymbolAddress((void**)&H2,   g_H2);
    cudaGetSymbolAddress((void**)&H3,   g_H3);

    // 1) LN on input
    ln_in_kernel<<<ROWS, D_MODEL>>>(x, norm_g, norm_b, XS);
    // 2) XP = XS @ in_w^T + in_b   (4096 x 192 x 192)
    gemm_abt<<<dim3(3, 64, 1), 256>>>(XS, in_w, in_b, XP,
                                      ROWS, D_MODEL, D_MODEL, 0, 0, 0, 1, 0);
    // 3) build direction sequences
    build_u_kernel<<<(NPAIR * NN * D_MODEL) / 256, 256>>>(XP, U);
    // 4) XZ = U @ m_in_w^T  (batched 16: 1024 x 768 x 192)
    gemm_abt<<<dim3(12, 16, 16), 256>>>(U, m_in_w, nullptr, XZ,
                                        NN, 2 * D_INNER, D_MODEL,
                                        (long)NN * D_MODEL, (long)2 * D_INNER * D_MODEL,
                                        (long)NN * 2 * D_INNER, 4, 0);
    // 5) causal conv + silu
    conv_silu_kernel<<<(NPAIR * NN * D_INNER) / 256, 256>>>(XZ, m_cw, m_cb, XSM);
    // 6) DBL = XSM @ m_xp_w^T  (batched 16: 1024 x 44 x 384)
    gemm_abt<<<dim3(1, 16, 16), 256>>>(XSM, m_xp_w, nullptr, DBL,
                                       NN, DBL_W, D_INNER,
                                       (long)NN * D_INNER, (long)DBL_W * D_INNER,
                                       (long)NN * DBL_W, 4, 0);
    // 7) dt projection + softplus
    dt_kernel<<<(NPAIR * NN * D_INNER) / 256, 256>>>(DBL, m_dt_w, m_dt_b, DT);
    // 8) selective scan
    scan_kernel<<<dim3(D_INNER / 8, 1, NPAIR), 128>>>(DT, XSM, DBL, m_Alog, Y);
    // 9) combine: (y + x*D) * silu(z)
    combine_kernel<<<(NPAIR * NN * D_INNER) / 256, 256>>>(Y, XSM, XZ, m_D, YG);
    // 10) OUTD = YG @ m_out_w^T  (batched 16: 1024 x 192 x 384)
    gemm_abt<<<dim3(3, 16, 16), 256>>>(YG, m_out_w, nullptr, OUTD,
                                       NN, D_MODEL, D_INNER,
                                       (long)NN * D_INNER, (long)D_MODEL * D_INNER,
                                       (long)NN * D_MODEL, 4, 0);
    // 11) gather into fused layout
    gather_kernel<<<(ROWS * 4 * D_MODEL) / 256, 256>>>(OUTD, FUS);
    // 12) H1 = gelu(FUS @ f_w1^T + f_b1)  (4096 x 384 x 768)
    gemm_abt<<<dim3(6, 64, 1), 256>>>(FUS, f_w1, f_b1, H1,
                                      ROWS, 2 * D_MODEL, 4 * D_MODEL, 0, 0, 0, 1, 2);
    // 13) H2 = H1 @ f_w2^T + f_b2  (4096 x 192 x 384)
    gemm_abt<<<dim3(3, 64, 1), 256>>>(H1, f_w2, f_b2, H2,
                                      ROWS, D_MODEL, 2 * D_MODEL, 0, 0, 0, 1, 0);
    // 14) H3 = H2 @ o_w^T + o_b  (4096 x 192 x 192)
    gemm_abt<<<dim3(3, 64, 1), 256>>>(H2, o_w, o_b, H3,
                                      ROWS, D_MODEL, D_MODEL, 0, 0, 0, 1, 0);
    // 15) final LN + residual + transpose
    ln_out_kernel<<<ROWS, D_MODEL>>>(H3, on_g, on_b, XS, out);
}